// round 6
// baseline (speedup 1.0000x reference)
#include <cuda_runtime.h>
#include <cuda_fp16.h>
#include <cstdint>

// SparseConv3d implicit GEMM.
// Device dtypes (harness-canonicalized): features fp32 [N,64], indices int32 [M,27],
// weight fp32 [27,64,64], out fp32 [M,64]. Values are exactly fp16-representable,
// so we convert to fp16 at staging and use HMMA with fp32 accumulation.

#define M_TILE   128
#define CIN      64
#define COUT     64
#define K3       27
#define A_STRIDE 72   // 144B row stride -> conflict-free ldmatrix phases
#define W_STRIDE 72
#define NTHREADS 256

__global__ __launch_bounds__(NTHREADS, 2)
void spconv_mma_kernel(const float* __restrict__ features,
                       const int* __restrict__ indices,
                       const float* __restrict__ weight,
                       float* __restrict__ out,
                       int M, int Nfeat)
{
    __shared__ __half sA[M_TILE][A_STRIDE];
    __shared__ __half sW[CIN][W_STRIDE];
    __shared__ int    sIdx[M_TILE][K3];

    const int t    = threadIdx.x;
    const int warp = t >> 5;
    const int lane = t & 31;
    const int base = blockIdx.x * M_TILE;

    // ---- stage indices for this tile ----
    for (int i = t; i < M_TILE * K3; i += NTHREADS) {
        int row  = i / K3;
        int kk   = i - row * K3;
        int grow = base + row;
        int v = (grow < M) ? indices[(long long)grow * K3 + kk] : -1;
        if (v < 0 || v >= Nfeat) v = -1;   // miss or defensive out-of-range
        sIdx[row][kk] = v;
    }

    // accumulators: per warp, m16 x n64 -> 8 n-tiles of m16n8, 4 floats each
    float acc[8][4];
#pragma unroll
    for (int i = 0; i < 8; ++i)
#pragma unroll
        for (int j = 0; j < 4; ++j) acc[i][j] = 0.f;

    // staging assignment: 4 threads per row, 16 floats each
    const int srow  = t >> 2;          // 0..63
    const int spart = (t & 3) * 16;    // float offset within row

    const int m0 = warp * 16;

    for (int k = 0; k < K3; ++k) {
        __syncthreads();   // protect sA/sW from previous iteration's consumers

        // ---- gather A tile (fp32 -> fp16): two passes of 64 rows ----
#pragma unroll
        for (int pass = 0; pass < 2; ++pass) {
            int row = srow + pass * 64;
            int gi  = sIdx[row][k];
            int4* dst = (int4*)&sA[row][spart];
            if (gi >= 0) {
                const float4* src = (const float4*)(features + (long long)gi * CIN + spart);
                float4 v0 = src[0], v1 = src[1], v2 = src[2], v3 = src[3];
                __half2 h[8];
                h[0] = __floats2half2_rn(v0.x, v0.y);
                h[1] = __floats2half2_rn(v0.z, v0.w);
                h[2] = __floats2half2_rn(v1.x, v1.y);
                h[3] = __floats2half2_rn(v1.z, v1.w);
                h[4] = __floats2half2_rn(v2.x, v2.y);
                h[5] = __floats2half2_rn(v2.z, v2.w);
                h[6] = __floats2half2_rn(v3.x, v3.y);
                h[7] = __floats2half2_rn(v3.z, v3.w);
                dst[0] = *(int4*)&h[0];
                dst[1] = *(int4*)&h[4];
            } else {
                int4 z = make_int4(0, 0, 0, 0);
                dst[0] = z; dst[1] = z;
            }
        }
        // ---- stage W[k] (64x64 fp32 -> fp16) ----
        {
            const float4* src = (const float4*)(weight + ((long long)k * CIN + srow) * COUT + spart);
            float4 v0 = src[0], v1 = src[1], v2 = src[2], v3 = src[3];
            __half2 h[8];
            h[0] = __floats2half2_rn(v0.x, v0.y);
            h[1] = __floats2half2_rn(v0.z, v0.w);
            h[2] = __floats2half2_rn(v1.x, v1.y);
            h[3] = __floats2half2_rn(v1.z, v1.w);
            h[4] = __floats2half2_rn(v2.x, v2.y);
            h[5] = __floats2half2_rn(v2.z, v2.w);
            h[6] = __floats2half2_rn(v3.x, v3.y);
            h[7] = __floats2half2_rn(v3.z, v3.w);
            int4* dst = (int4*)&sW[srow][spart];
            dst[0] = *(int4*)&h[0];
            dst[1] = *(int4*)&h[4];
        }
        __syncthreads();

        // ---- m16 x n64 x k64 per warp via mma.m16n8k16 ----
#pragma unroll
        for (int ks = 0; ks < 4; ++ks) {
            uint32_t a0, a1, a2, a3;
            {
                int r = m0 + (lane & 15);
                int c = ks * 16 + ((lane >> 4) << 3);
                uint32_t addr = (uint32_t)__cvta_generic_to_shared(&sA[r][c]);
                asm volatile("ldmatrix.sync.aligned.m8n8.x4.shared.b16 {%0,%1,%2,%3}, [%4];\n"
                             : "=r"(a0), "=r"(a1), "=r"(a2), "=r"(a3) : "r"(addr));
            }
#pragma unroll
            for (int nt = 0; nt < 4; ++nt) {   // each iter covers 2 n-tiles (16 cols)
                uint32_t b0, b1, b2, b3;
                {
                    int g    = lane >> 3;
                    int l8   = lane & 7;
                    int krow = ks * 16 + l8 + ((g & 1) << 3);
                    int ncol = nt * 16 + ((g >> 1) << 3);
                    uint32_t addr = (uint32_t)__cvta_generic_to_shared(&sW[krow][ncol]);
                    asm volatile("ldmatrix.sync.aligned.m8n8.x4.trans.shared.b16 {%0,%1,%2,%3}, [%4];\n"
                                 : "=r"(b0), "=r"(b1), "=r"(b2), "=r"(b3) : "r"(addr));
                }
                asm volatile("mma.sync.aligned.m16n8k16.row.col.f32.f16.f16.f32 "
                             "{%0,%1,%2,%3},{%4,%5,%6,%7},{%8,%9},{%0,%1,%2,%3};\n"
                             : "+f"(acc[2*nt][0]), "+f"(acc[2*nt][1]),
                               "+f"(acc[2*nt][2]), "+f"(acc[2*nt][3])
                             : "r"(a0), "r"(a1), "r"(a2), "r"(a3), "r"(b0), "r"(b1));
                asm volatile("mma.sync.aligned.m16n8k16.row.col.f32.f16.f16.f32 "
                             "{%0,%1,%2,%3},{%4,%5,%6,%7},{%8,%9},{%0,%1,%2,%3};\n"
                             : "+f"(acc[2*nt+1][0]), "+f"(acc[2*nt+1][1]),
                               "+f"(acc[2*nt+1][2]), "+f"(acc[2*nt+1][3])
                             : "r"(a0), "r"(a1), "r"(a2), "r"(a3), "r"(b2), "r"(b3));
            }
        }
    }

    // ---- epilogue: fp32 acc -> fp16 rounding (to match reference) -> fp32 store ----
    {
        const int g  = lane >> 2;          // row-in-tile 0..7
        const int cc = (lane & 3) * 2;     // col pair base
        const int row0 = base + m0 + g;
        const int row1 = row0 + 8;
#pragma unroll
        for (int nt = 0; nt < 8; ++nt) {
            int col = nt * 8 + cc;
            if (row0 < M) {
                float2 v;
                v.x = __half2float(__float2half_rn(acc[nt][0]));
                v.y = __half2float(__float2half_rn(acc[nt][1]));
                *(float2*)(out + (long long)row0 * COUT + col) = v;
            }
            if (row1 < M) {
                float2 v;
                v.x = __half2float(__float2half_rn(acc[nt][2]));
                v.y = __half2float(__float2half_rn(acc[nt][3]));
                *(float2*)(out + (long long)row1 * COUT + col) = v;
            }
        }
    }
}

extern "C" void kernel_launch(void* const* d_in, const int* in_sizes, int n_in,
                              void* d_out, int out_size)
{
    const float* features = (const float*)d_in[0];
    const int*   indices  = (const int*)d_in[1];
    const float* weight   = (const float*)d_in[2];
    float*       out      = (float*)d_out;

    const int M     = out_size / COUT;       // 200000
    const int Nfeat = in_sizes[0] / CIN;     // 200000
    const int grid  = (M + M_TILE - 1) / M_TILE;

    spconv_mma_kernel<<<grid, NTHREADS>>>(features, indices, weight, out, M, Nfeat);
}

// round 8
// speedup vs baseline: 1.6829x; 1.6829x over previous
#include <cuda_runtime.h>
#include <cuda_fp16.h>
#include <cstdint>

// SparseConv3d implicit GEMM, round 7.
// Device dtypes (harness-canonicalized): features fp32 [N,64], indices int32 [M,27],
// weight fp32 [27,64,64], out fp32 [M,64]. Values exactly fp16-representable ->
// convert at staging, HMMA fp16 with fp32 accumulation.
//
// R7 changes vs R6 (385us, L1tex 69.7% = bottleneck):
//  - coalesced gather: 16 threads/row x 16B  (halves LDG wavefronts)
//  - 4x2 warp tiling (warp = m32 x n32)      (halves ldmatrix-B redundancy)
//  - register double-buffer: prefetch A/W(k+1) during MMA(k)  (hides LDG latency)

#define M_TILE   128
#define CIN      64
#define COUT     64
#define K3       27
#define A_STRIDE 72   // halves; 144B row stride -> conflict-free ldmatrix phases
#define W_STRIDE 72
#define NTHREADS 256

__global__ __launch_bounds__(NTHREADS, 2)
void spconv_mma_kernel(const float* __restrict__ features,
                       const int* __restrict__ indices,
                       const float* __restrict__ weight,
                       float* __restrict__ out,
                       int M, int Nfeat)
{
    __shared__ __half sA[M_TILE][A_STRIDE];
    __shared__ __half sW[CIN][W_STRIDE];
    __shared__ int    sIdx[M_TILE][K3];

    const int t    = threadIdx.x;
    const int warp = t >> 5;
    const int lane = t & 31;
    const int base = blockIdx.x * M_TILE;

    const int wm = warp >> 1;      // 0..3 -> m offset wm*32
    const int wn = warp & 1;       // 0..1 -> n offset wn*32

    // ---- stage indices for this tile ----
    for (int i = t; i < M_TILE * K3; i += NTHREADS) {
        int row  = i / K3;
        int kk   = i - row * K3;
        int grow = base + row;
        int v = (grow < M) ? indices[(long long)grow * K3 + kk] : -1;
        if (v < 0 || v >= Nfeat) v = -1;
        sIdx[row][kk] = v;
    }
    __syncthreads();   // sIdx ready for prefetch

    // prefetch assignment: 16 threads per row, 16B (4 floats) each
    const int prow = t >> 4;          // 0..15
    const int pcol = (t & 15) * 4;    // float offset within row

    float4 pf[8];    // A rows prow+16p, p=0..7
    float4 wpf[4];   // W rows prow+16p, p=0..3

    // ---- prefetch k = 0 ----
#pragma unroll
    for (int p = 0; p < 8; ++p) {
        int row = prow + p * 16;
        int gi  = sIdx[row][0];
        if (gi >= 0)
            pf[p] = *(const float4*)(features + (long long)gi * CIN + pcol);
        else
            pf[p] = make_float4(0.f, 0.f, 0.f, 0.f);
    }
#pragma unroll
    for (int p = 0; p < 4; ++p) {
        int wrow = prow + p * 16;
        wpf[p] = *(const float4*)(weight + (long long)(0 * CIN + wrow) * COUT + pcol);
    }

    float acc[2][4][4];
#pragma unroll
    for (int a = 0; a < 2; ++a)
#pragma unroll
        for (int b = 0; b < 4; ++b)
#pragma unroll
            for (int c = 0; c < 4; ++c) acc[a][b][c] = 0.f;

    for (int k = 0; k < K3; ++k) {
        __syncthreads();   // consumers of previous tile done

        // ---- store staged A (fp32 regs -> fp16 smem) ----
#pragma unroll
        for (int p = 0; p < 8; ++p) {
            int row = prow + p * 16;
            __half2 h0 = __floats2half2_rn(pf[p].x, pf[p].y);
            __half2 h1 = __floats2half2_rn(pf[p].z, pf[p].w);
            uint2 v;
            v.x = *(uint32_t*)&h0;
            v.y = *(uint32_t*)&h1;
            *(uint2*)&sA[row][pcol] = v;
        }
        // ---- store staged W ----
#pragma unroll
        for (int p = 0; p < 4; ++p) {
            int wrow = prow + p * 16;
            __half2 h0 = __floats2half2_rn(wpf[p].x, wpf[p].y);
            __half2 h1 = __floats2half2_rn(wpf[p].z, wpf[p].w);
            uint2 v;
            v.x = *(uint32_t*)&h0;
            v.y = *(uint32_t*)&h1;
            *(uint2*)&sW[wrow][pcol] = v;
        }
        __syncthreads();

        // ---- prefetch k+1 while MMAs run ----
        if (k + 1 < K3) {
#pragma unroll
            for (int p = 0; p < 8; ++p) {
                int row = prow + p * 16;
                int gi  = sIdx[row][k + 1];
                if (gi >= 0)
                    pf[p] = *(const float4*)(features + (long long)gi * CIN + pcol);
                else
                    pf[p] = make_float4(0.f, 0.f, 0.f, 0.f);
            }
#pragma unroll
            for (int p = 0; p < 4; ++p) {
                int wrow = prow + p * 16;
                wpf[p] = *(const float4*)(weight + (long long)((k + 1) * CIN + wrow) * COUT + pcol);
            }
        }

        // ---- warp tile m32 x n32 x k64 via mma.m16n8k16 ----
#pragma unroll
        for (int ks = 0; ks < 4; ++ks) {
            uint32_t af[2][4];
#pragma unroll
            for (int mt = 0; mt < 2; ++mt) {
                int r = wm * 32 + mt * 16 + (lane & 15);
                int c = ks * 16 + ((lane >> 4) << 3);
                uint32_t addr = (uint32_t)__cvta_generic_to_shared(&sA[r][c]);
                asm volatile("ldmatrix.sync.aligned.m8n8.x4.shared.b16 {%0,%1,%2,%3}, [%4];\n"
                             : "=r"(af[mt][0]), "=r"(af[mt][1]),
                               "=r"(af[mt][2]), "=r"(af[mt][3]) : "r"(addr));
            }
#pragma unroll
            for (int nt = 0; nt < 2; ++nt) {
                uint32_t b0, b1, b2, b3;
                {
                    int g    = lane >> 3;
                    int l8   = lane & 7;
                    int krow = ks * 16 + l8 + ((g & 1) << 3);
                    int ncol = wn * 32 + nt * 16 + ((g >> 1) << 3);
                    uint32_t addr = (uint32_t)__cvta_generic_to_shared(&sW[krow][ncol]);
                    asm volatile("ldmatrix.sync.aligned.m8n8.x4.trans.shared.b16 {%0,%1,%2,%3}, [%4];\n"
                                 : "=r"(b0), "=r"(b1), "=r"(b2), "=r"(b3) : "r"(addr));
                }
#pragma unroll
                for (int mt = 0; mt < 2; ++mt) {
                    asm volatile("mma.sync.aligned.m16n8k16.row.col.f32.f16.f16.f32 "
                                 "{%0,%1,%2,%3},{%4,%5,%6,%7},{%8,%9},{%0,%1,%2,%3};\n"
                                 : "+f"(acc[mt][2*nt][0]), "+f"(acc[mt][2*nt][1]),
                                   "+f"(acc[mt][2*nt][2]), "+f"(acc[mt][2*nt][3])
                                 : "r"(af[mt][0]), "r"(af[mt][1]), "r"(af[mt][2]), "r"(af[mt][3]),
                                   "r"(b0), "r"(b1));
                    asm volatile("mma.sync.aligned.m16n8k16.row.col.f32.f16.f16.f32 "
                                 "{%0,%1,%2,%3},{%4,%5,%6,%7},{%8,%9},{%0,%1,%2,%3};\n"
                                 : "+f"(acc[mt][2*nt+1][0]), "+f"(acc[mt][2*nt+1][1]),
                                   "+f"(acc[mt][2*nt+1][2]), "+f"(acc[mt][2*nt+1][3])
                                 : "r"(af[mt][0]), "r"(af[mt][1]), "r"(af[mt][2]), "r"(af[mt][3]),
                                   "r"(b2), "r"(b3));
                }
            }
        }
    }

    // ---- epilogue: fp32 acc -> fp16 rounding (match reference) -> fp32 store ----
    {
        const int g  = lane >> 2;          // 0..7
        const int cc = (lane & 3) * 2;
#pragma unroll
        for (int mt = 0; mt < 2; ++mt) {
            const int row0 = base + wm * 32 + mt * 16 + g;
            const int row1 = row0 + 8;
#pragma unroll
            for (int nt8 = 0; nt8 < 4; ++nt8) {
                int col = wn * 32 + nt8 * 8 + cc;
                if (row0 < M) {
                    float2 v;
                    v.x = __half2float(__float2half_rn(acc[mt][nt8][0]));
                    v.y = __half2float(__float2half_rn(acc[mt][nt8][1]));
                    *(float2*)(out + (long long)row0 * COUT + col) = v;
                }
                if (row1 < M) {
                    float2 v;
                    v.x = __half2float(__float2half_rn(acc[mt][nt8][2]));
                    v.y = __half2float(__float2half_rn(acc[mt][nt8][3]));
                    *(float2*)(out + (long long)row1 * COUT + col) = v;
                }
            }
        }
    }
}

extern "C" void kernel_launch(void* const* d_in, const int* in_sizes, int n_in,
                              void* d_out, int out_size)
{
    const float* features = (const float*)d_in[0];
    const int*   indices  = (const int*)d_in[1];
    const float* weight   = (const float*)d_in[2];
    float*       out      = (float*)d_out;

    const int M     = out_size / COUT;       // 200000
    const int Nfeat = in_sizes[0] / CIN;     // 200000
    const int grid  = (M + M_TILE - 1) / M_TILE;

    spconv_mma_kernel<<<grid, NTHREADS>>>(features, indices, weight, out, M, Nfeat);
}

// round 11
// speedup vs baseline: 2.1622x; 1.2848x over previous
#include <cuda_runtime.h>
#include <cuda_fp16.h>
#include <cstdint>

// SparseConv3d implicit GEMM, round 11 (= R10 minus the static-guard rule risk).
// tcgen05 unavailable (harness builds compute_103 PTX). HMMA path, optimized:
//  - pre-pass converts features+weight fp32 -> fp16 into __device__ scratch
//  - main kernel: cp.async gather (16B, zero-fill for misses) + 2-stage double buffer
//  - 8 warps, warp tile m32 x n32, mma.m16n8k16 fp16 -> fp32 acc

#define M_TILE   128
#define CIN      64
#define COUT     64
#define K3       27
#define NTHREADS 256
#define NFEAT_MAX 200000

#define A_STRIDE 72   // halves; 144B row stride, conflict-free ldmatrix, 16B-aligned chunks
#define W_STRIDE 72

// dynamic smem layout (bytes)
#define SIDX_BYTES   (M_TILE * K3 * 4)          // 13824
#define BUF_OFF      14336                       // 1KB-aligned start of tile buffers
#define A_BYTES      (M_TILE * A_STRIDE * 2)     // 18432
#define W_BYTES      (CIN * W_STRIDE * 2)        // 9216
#define SMEM_TOTAL   (BUF_OFF + 2 * (A_BYTES + W_BYTES))   // 69632

__device__ __half g_featH[(size_t)NFEAT_MAX * CIN];
__device__ __half g_wH[K3 * CIN * COUT];

__device__ __forceinline__ uint32_t smem_u32(const void* p) {
    return (uint32_t)__cvta_generic_to_shared(p);
}

// ---------------- pre-pass: fp32 -> fp16 ----------------
__global__ void convert_kernel(const float* __restrict__ feat,
                               const float* __restrict__ wgt,
                               int nfeat_elems, int nw_elems)
{
    const int nf4 = nfeat_elems >> 2;
    const int nw4 = nw_elems >> 2;
    for (int i = blockIdx.x * blockDim.x + threadIdx.x; i < nf4 + nw4;
         i += gridDim.x * blockDim.x) {
        if (i < nf4) {
            float4 v = ((const float4*)feat)[i];
            __half2 h0 = __floats2half2_rn(v.x, v.y);
            __half2 h1 = __floats2half2_rn(v.z, v.w);
            uint2 o; o.x = *(uint32_t*)&h0; o.y = *(uint32_t*)&h1;
            ((uint2*)g_featH)[i] = o;
        } else {
            int j = i - nf4;
            float4 v = ((const float4*)wgt)[j];
            __half2 h0 = __floats2half2_rn(v.x, v.y);
            __half2 h1 = __floats2half2_rn(v.z, v.w);
            uint2 o; o.x = *(uint32_t*)&h0; o.y = *(uint32_t*)&h1;
            ((uint2*)g_wH)[j] = o;
        }
    }
}

// ---------------- main kernel ----------------
__device__ __forceinline__ void issue_tile_copies(int k, char* smem, int bsel, const int* sIdx, int t)
{
    __half* sA = (__half*)(smem + BUF_OFF + bsel * (A_BYTES + W_BYTES));
    __half* sW = (__half*)(smem + BUF_OFF + bsel * (A_BYTES + W_BYTES) + A_BYTES);

    const int tr = t >> 3;          // 0..31
    const int tc = (t & 7) * 8;     // halves offset (16B chunk)

#pragma unroll
    for (int p = 0; p < 4; ++p) {
        int row = tr + p * 32;
        int gi  = sIdx[row * K3 + k];
        const __half* src = g_featH + (size_t)max(gi, 0) * CIN + tc;
        uint32_t dst = smem_u32(&sA[row * A_STRIDE + tc]);
        int sz = (gi >= 0) ? 16 : 0;
        asm volatile("cp.async.cg.shared.global [%0], [%1], 16, %2;\n"
                     :: "r"(dst), "l"(src), "r"(sz));
    }
#pragma unroll
    for (int p = 0; p < 2; ++p) {
        int row = tr + p * 32;
        const __half* src = g_wH + ((size_t)k * CIN + row) * COUT + tc;
        uint32_t dst = smem_u32(&sW[row * W_STRIDE + tc]);
        asm volatile("cp.async.cg.shared.global [%0], [%1], 16;\n"
                     :: "r"(dst), "l"(src));
    }
    asm volatile("cp.async.commit_group;\n" ::: "memory");
}

__global__ __launch_bounds__(NTHREADS, 3)
void spconv_mma_kernel(const int* __restrict__ indices,
                       float* __restrict__ out,
                       int M, int Nfeat)
{
    extern __shared__ char smem[];
    int* sIdx = (int*)smem;

    const int t    = threadIdx.x;
    const int warp = t >> 5;
    const int lane = t & 31;
    const int base = blockIdx.x * M_TILE;

    const int wm = warp >> 1;      // 0..3 -> m offset wm*32
    const int wn = warp & 1;       // 0..1 -> n offset wn*32

    // ---- stage indices ----
    for (int i = t; i < M_TILE * K3; i += NTHREADS) {
        int row  = i / K3;
        int kk   = i - row * K3;
        int grow = base + row;
        int v = (grow < M) ? indices[(long long)grow * K3 + kk] : -1;
        if (v < 0 || v >= Nfeat) v = -1;
        sIdx[row * K3 + kk] = v;
    }
    __syncthreads();

    // ---- prologue: stages 0 and 1 in flight ----
    issue_tile_copies(0, smem, 0, sIdx, t);
    issue_tile_copies(1, smem, 1, sIdx, t);

    float acc[2][4][4];
#pragma unroll
    for (int a = 0; a < 2; ++a)
#pragma unroll
        for (int b = 0; b < 4; ++b)
#pragma unroll
            for (int c = 0; c < 4; ++c) acc[a][b][c] = 0.f;

    for (int k = 0; k < K3; ++k) {
        const int bsel = k & 1;
        if (k == K3 - 1)
            asm volatile("cp.async.wait_group 0;\n" ::: "memory");
        else
            asm volatile("cp.async.wait_group 1;\n" ::: "memory");
        __syncthreads();   // stage k visible to all warps

        const uint32_t aB = smem_u32(smem + BUF_OFF + bsel * (A_BYTES + W_BYTES));
        const uint32_t wB = aB + A_BYTES;

        // ---- warp tile m32 x n32 x k64 ----
#pragma unroll
        for (int ks = 0; ks < 4; ++ks) {
            uint32_t af[2][4];
#pragma unroll
            for (int mt = 0; mt < 2; ++mt) {
                int r = wm * 32 + mt * 16 + (lane & 15);
                int c = ks * 16 + ((lane >> 4) << 3);
                uint32_t addr = aB + (uint32_t)(r * A_STRIDE + c) * 2u;
                asm volatile("ldmatrix.sync.aligned.m8n8.x4.shared.b16 {%0,%1,%2,%3}, [%4];\n"
                             : "=r"(af[mt][0]), "=r"(af[mt][1]),
                               "=r"(af[mt][2]), "=r"(af[mt][3]) : "r"(addr));
            }
#pragma unroll
            for (int nt = 0; nt < 2; ++nt) {
                uint32_t b0, b1, b2, b3;
                {
                    int g    = lane >> 3;
                    int l8   = lane & 7;
                    int krow = ks * 16 + l8 + ((g & 1) << 3);
                    int ncol = wn * 32 + nt * 16 + ((g >> 1) << 3);
                    uint32_t addr = wB + (uint32_t)(krow * W_STRIDE + ncol) * 2u;
                    asm volatile("ldmatrix.sync.aligned.m8n8.x4.trans.shared.b16 {%0,%1,%2,%3}, [%4];\n"
                                 : "=r"(b0), "=r"(b1), "=r"(b2), "=r"(b3) : "r"(addr));
                }
#pragma unroll
                for (int mt = 0; mt < 2; ++mt) {
                    asm volatile("mma.sync.aligned.m16n8k16.row.col.f32.f16.f16.f32 "
                                 "{%0,%1,%2,%3},{%4,%5,%6,%7},{%8,%9},{%0,%1,%2,%3};\n"
                                 : "+f"(acc[mt][2*nt][0]), "+f"(acc[mt][2*nt][1]),
                                   "+f"(acc[mt][2*nt][2]), "+f"(acc[mt][2*nt][3])
                                 : "r"(af[mt][0]), "r"(af[mt][1]), "r"(af[mt][2]), "r"(af[mt][3]),
                                   "r"(b0), "r"(b1));
                    asm volatile("mma.sync.aligned.m16n8k16.row.col.f32.f16.f16.f32 "
                                 "{%0,%1,%2,%3},{%4,%5,%6,%7},{%8,%9},{%0,%1,%2,%3};\n"
                                 : "+f"(acc[mt][2*nt+1][0]), "+f"(acc[mt][2*nt+1][1]),
                                   "+f"(acc[mt][2*nt+1][2]), "+f"(acc[mt][2*nt+1][3])
                                 : "r"(af[mt][0]), "r"(af[mt][1]), "r"(af[mt][2]), "r"(af[mt][3]),
                                   "r"(b2), "r"(b3));
                }
            }
        }

        __syncthreads();   // all warps done with stage k's buffer
        if (k + 2 < K3)
            issue_tile_copies(k + 2, smem, bsel, sIdx, t);
    }

    // ---- epilogue: fp32 acc -> fp16 rounding (match reference) -> fp32 store ----
    {
        const int g  = lane >> 2;
        const int cc = (lane & 3) * 2;
#pragma unroll
        for (int mt = 0; mt < 2; ++mt) {
            const int row0 = base + wm * 32 + mt * 16 + g;
            const int row1 = row0 + 8;
#pragma unroll
            for (int nt8 = 0; nt8 < 4; ++nt8) {
                int col = wn * 32 + nt8 * 8 + cc;
                if (row0 < M) {
                    float2 v;
                    v.x = __half2float(__float2half_rn(acc[mt][nt8][0]));
                    v.y = __half2float(__float2half_rn(acc[mt][nt8][1]));
                    *(float2*)(out + (long long)row0 * COUT + col) = v;
                }
                if (row1 < M) {
                    float2 v;
                    v.x = __half2float(__float2half_rn(acc[mt][nt8][2]));
                    v.y = __half2float(__float2half_rn(acc[mt][nt8][3]));
                    *(float2*)(out + (long long)row1 * COUT + col) = v;
                }
            }
        }
    }
}

extern "C" void kernel_launch(void* const* d_in, const int* in_sizes, int n_in,
                              void* d_out, int out_size)
{
    const float* features = (const float*)d_in[0];
    const int*   indices  = (const int*)d_in[1];
    const float* weight   = (const float*)d_in[2];
    float*       out      = (float*)d_out;

    const int M     = out_size / COUT;       // 200000
    const int Nfeat = in_sizes[0] / CIN;     // 200000
    const int grid  = (M + M_TILE - 1) / M_TILE;

    // unconditional (no static guards): idempotent, capture-safe attribute set
    cudaFuncSetAttribute(spconv_mma_kernel,
                         cudaFuncAttributeMaxDynamicSharedMemorySize, SMEM_TOTAL);

    convert_kernel<<<512, 256>>>(features, weight, Nfeat * CIN, K3 * CIN * COUT);
    spconv_mma_kernel<<<grid, NTHREADS, SMEM_TOTAL>>>(indices, out, M, Nfeat);
}

// round 12
// speedup vs baseline: 2.3223x; 1.0740x over previous
#include <cuda_runtime.h>
#include <cuda_fp16.h>
#include <cstdint>

// SparseConv3d implicit GEMM, round 12.
// R11 (178.3us) analysis: smem crossbar bound (L1 71% == 91/128 B/cyc model).
// R12: 4 warps (2x2 split), warp tile m64 x n32 -> fragment re-reads drop
//      A2x+B4x (64KB/k) -> A2x+B2x (48KB/k); total smem traffic 0.82x.
//  - pre-pass converts features+weight fp32 -> fp16 into __device__ scratch
//  - cp.async gather (16B, zero-fill for misses) + 2-stage double buffer

#define M_TILE   128
#define CIN      64
#define COUT     64
#define K3       27
#define NTHREADS 128
#define NFEAT_MAX 200000

#define A_STRIDE 72   // halves; 144B row stride, conflict-free ldmatrix, 16B-aligned chunks
#define W_STRIDE 72

// dynamic smem layout (bytes)
#define BUF_OFF      14336                       // 1KB-aligned start of tile buffers (sIdx = 13824)
#define A_BYTES      (M_TILE * A_STRIDE * 2)     // 18432
#define W_BYTES      (CIN * W_STRIDE * 2)        // 9216
#define SMEM_TOTAL   (BUF_OFF + 2 * (A_BYTES + W_BYTES))   // 69632

__device__ __half g_featH[(size_t)NFEAT_MAX * CIN];
__device__ __half g_wH[K3 * CIN * COUT];

__device__ __forceinline__ uint32_t smem_u32(const void* p) {
    return (uint32_t)__cvta_generic_to_shared(p);
}

// ---------------- pre-pass: fp32 -> fp16 ----------------
__global__ void convert_kernel(const float* __restrict__ feat,
                               const float* __restrict__ wgt,
                               int nfeat_elems, int nw_elems)
{
    const int nf4 = nfeat_elems >> 2;
    const int nw4 = nw_elems >> 2;
    for (int i = blockIdx.x * blockDim.x + threadIdx.x; i < nf4 + nw4;
         i += gridDim.x * blockDim.x) {
        if (i < nf4) {
            float4 v = ((const float4*)feat)[i];
            __half2 h0 = __floats2half2_rn(v.x, v.y);
            __half2 h1 = __floats2half2_rn(v.z, v.w);
            uint2 o; o.x = *(uint32_t*)&h0; o.y = *(uint32_t*)&h1;
            ((uint2*)g_featH)[i] = o;
        } else {
            int j = i - nf4;
            float4 v = ((const float4*)wgt)[j];
            __half2 h0 = __floats2half2_rn(v.x, v.y);
            __half2 h1 = __floats2half2_rn(v.z, v.w);
            uint2 o; o.x = *(uint32_t*)&h0; o.y = *(uint32_t*)&h1;
            ((uint2*)g_wH)[j] = o;
        }
    }
}

// ---------------- main kernel ----------------
__device__ __forceinline__ void issue_tile_copies(int k, char* smem, int bsel, const int* sIdx, int t)
{
    __half* sA = (__half*)(smem + BUF_OFF + bsel * (A_BYTES + W_BYTES));
    __half* sW = (__half*)(smem + BUF_OFF + bsel * (A_BYTES + W_BYTES) + A_BYTES);

    const int tr = t >> 3;          // 0..15
    const int tc = (t & 7) * 8;     // halves offset (16B chunk)

#pragma unroll
    for (int p = 0; p < 8; ++p) {
        int row = tr + p * 16;
        int gi  = sIdx[row * K3 + k];
        const __half* src = g_featH + (size_t)max(gi, 0) * CIN + tc;
        uint32_t dst = smem_u32(&sA[row * A_STRIDE + tc]);
        int sz = (gi >= 0) ? 16 : 0;
        asm volatile("cp.async.cg.shared.global [%0], [%1], 16, %2;\n"
                     :: "r"(dst), "l"(src), "r"(sz));
    }
#pragma unroll
    for (int p = 0; p < 4; ++p) {
        int row = tr + p * 16;
        const __half* src = g_wH + ((size_t)k * CIN + row) * COUT + tc;
        uint32_t dst = smem_u32(&sW[row * W_STRIDE + tc]);
        asm volatile("cp.async.cg.shared.global [%0], [%1], 16;\n"
                     :: "r"(dst), "l"(src));
    }
    asm volatile("cp.async.commit_group;\n" ::: "memory");
}

__global__ __launch_bounds__(NTHREADS, 3)
void spconv_mma_kernel(const int* __restrict__ indices,
                       float* __restrict__ out,
                       int M, int Nfeat)
{
    extern __shared__ char smem[];
    int* sIdx = (int*)smem;

    const int t    = threadIdx.x;
    const int warp = t >> 5;       // 0..3
    const int lane = t & 31;
    const int base = blockIdx.x * M_TILE;

    const int wm = warp >> 1;      // 0..1 -> m offset wm*64
    const int wn = warp & 1;       // 0..1 -> n offset wn*32

    // ---- stage indices ----
    for (int i = t; i < M_TILE * K3; i += NTHREADS) {
        int row  = i / K3;
        int kk   = i - row * K3;
        int grow = base + row;
        int v = (grow < M) ? indices[(long long)grow * K3 + kk] : -1;
        if (v < 0 || v >= Nfeat) v = -1;
        sIdx[row * K3 + kk] = v;
    }
    __syncthreads();

    // ---- prologue: stages 0 and 1 in flight ----
    issue_tile_copies(0, smem, 0, sIdx, t);
    issue_tile_copies(1, smem, 1, sIdx, t);

    // warp tile m64 x n32: acc[mt 0..3][n8-tile 0..3][4]
    float acc[4][4][4];
#pragma unroll
    for (int a = 0; a < 4; ++a)
#pragma unroll
        for (int b = 0; b < 4; ++b)
#pragma unroll
            for (int c = 0; c < 4; ++c) acc[a][b][c] = 0.f;

    for (int k = 0; k < K3; ++k) {
        const int bsel = k & 1;
        if (k == K3 - 1)
            asm volatile("cp.async.wait_group 0;\n" ::: "memory");
        else
            asm volatile("cp.async.wait_group 1;\n" ::: "memory");
        __syncthreads();   // stage k visible to all warps

        const uint32_t aB = smem_u32(smem + BUF_OFF + bsel * (A_BYTES + W_BYTES));
        const uint32_t wB = aB + A_BYTES;

        // ---- warp tile m64 x n32 x k64 ----
#pragma unroll
        for (int ks = 0; ks < 4; ++ks) {
            uint32_t af[4][4];
#pragma unroll
            for (int mt = 0; mt < 4; ++mt) {
                int r = wm * 64 + mt * 16 + (lane & 15);
                int c = ks * 16 + ((lane >> 4) << 3);
                uint32_t addr = aB + (uint32_t)(r * A_STRIDE + c) * 2u;
                asm volatile("ldmatrix.sync.aligned.m8n8.x4.shared.b16 {%0,%1,%2,%3}, [%4];\n"
                             : "=r"(af[mt][0]), "=r"(af[mt][1]),
                               "=r"(af[mt][2]), "=r"(af[mt][3]) : "r"(addr));
            }
#pragma unroll
            for (int nt = 0; nt < 2; ++nt) {
                uint32_t b0, b1, b2, b3;
                {
                    int g    = lane >> 3;
                    int l8   = lane & 7;
                    int krow = ks * 16 + l8 + ((g & 1) << 3);
                    int ncol = wn * 32 + nt * 16 + ((g >> 1) << 3);
                    uint32_t addr = wB + (uint32_t)(krow * W_STRIDE + ncol) * 2u;
                    asm volatile("ldmatrix.sync.aligned.m8n8.x4.trans.shared.b16 {%0,%1,%2,%3}, [%4];\n"
                                 : "=r"(b0), "=r"(b1), "=r"(b2), "=r"(b3) : "r"(addr));
                }
#pragma unroll
                for (int mt = 0; mt < 4; ++mt) {
                    asm volatile("mma.sync.aligned.m16n8k16.row.col.f32.f16.f16.f32 "
                                 "{%0,%1,%2,%3},{%4,%5,%6,%7},{%8,%9},{%0,%1,%2,%3};\n"
                                 : "+f"(acc[mt][2*nt][0]), "+f"(acc[mt][2*nt][1]),
                                   "+f"(acc[mt][2*nt][2]), "+f"(acc[mt][2*nt][3])
                                 : "r"(af[mt][0]), "r"(af[mt][1]), "r"(af[mt][2]), "r"(af[mt][3]),
                                   "r"(b0), "r"(b1));
                    asm volatile("mma.sync.aligned.m16n8k16.row.col.f32.f16.f16.f32 "
                                 "{%0,%1,%2,%3},{%4,%5,%6,%7},{%8,%9},{%0,%1,%2,%3};\n"
                                 : "+f"(acc[mt][2*nt+1][0]), "+f"(acc[mt][2*nt+1][1]),
                                   "+f"(acc[mt][2*nt+1][2]), "+f"(acc[mt][2*nt+1][3])
                                 : "r"(af[mt][0]), "r"(af[mt][1]), "r"(af[mt][2]), "r"(af[mt][3]),
                                   "r"(b2), "r"(b3));
                }
            }
        }

        __syncthreads();   // all warps done with stage k's buffer
        if (k + 2 < K3)
            issue_tile_copies(k + 2, smem, bsel, sIdx, t);
    }

    // ---- epilogue: fp32 acc -> fp16 rounding (match reference) -> fp32 store ----
    {
        const int g  = lane >> 2;
        const int cc = (lane & 3) * 2;
#pragma unroll
        for (int mt = 0; mt < 4; ++mt) {
            const int row0 = base + wm * 64 + mt * 16 + g;
            const int row1 = row0 + 8;
#pragma unroll
            for (int nt8 = 0; nt8 < 4; ++nt8) {
                int col = wn * 32 + nt8 * 8 + cc;
                if (row0 < M) {
                    float2 v;
                    v.x = __half2float(__float2half_rn(acc[mt][nt8][0]));
                    v.y = __half2float(__float2half_rn(acc[mt][nt8][1]));
                    *(float2*)(out + (long long)row0 * COUT + col) = v;
                }
                if (row1 < M) {
                    float2 v;
                    v.x = __half2float(__float2half_rn(acc[mt][nt8][2]));
                    v.y = __half2float(__float2half_rn(acc[mt][nt8][3]));
                    *(float2*)(out + (long long)row1 * COUT + col) = v;
                }
            }
        }
    }
}

extern "C" void kernel_launch(void* const* d_in, const int* in_sizes, int n_in,
                              void* d_out, int out_size)
{
    const float* features = (const float*)d_in[0];
    const int*   indices  = (const int*)d_in[1];
    const float* weight   = (const float*)d_in[2];
    float*       out      = (float*)d_out;

    const int M     = out_size / COUT;       // 200000
    const int Nfeat = in_sizes[0] / CIN;     // 200000
    const int grid  = (M + M_TILE - 1) / M_TILE;

    // unconditional (no static guards): idempotent, capture-safe attribute set
    cudaFuncSetAttribute(spconv_mma_kernel,
                         cudaFuncAttributeMaxDynamicSharedMemorySize, SMEM_TOTAL);

    convert_kernel<<<1024, 256>>>(features, weight, Nfeat * CIN, K3 * CIN * COUT);
    spconv_mma_kernel<<<grid, NTHREADS, SMEM_TOTAL>>>(indices, out, M, Nfeat);
}

// round 13
// speedup vs baseline: 2.5090x; 1.0804x over previous
#include <cuda_runtime.h>
#include <cuda_fp16.h>
#include <cstdint>

// SparseConv3d implicit GEMM, round 13.
// R12 (148.6us main): 12 warps/SM, nothing saturated -> latency-bound.
// R13: 4 CTAs/SM (16 warps): drop sIdx smem staging (read indices direct via __ldg),
//      cap regs via __launch_bounds__(128,4). smem 55.3KB/CTA -> 4x221KB fits.
//  - pre-pass converts features+weight fp32 -> fp16 into __device__ scratch
//  - cp.async gather (16B, zero-fill for misses) + 2-stage double buffer
//  - 4 warps, warp tile m64 x n32 (A2x + B2x smem re-read = minimal)

#define M_TILE   128
#define CIN      64
#define COUT     64
#define K3       27
#define NTHREADS 128
#define NFEAT_MAX 200000

#define A_STRIDE 72   // halves; 144B row stride, conflict-free ldmatrix, 16B-aligned chunks
#define W_STRIDE 72

// dynamic smem layout (bytes): two stages of (A | W), no index staging
#define A_BYTES      (M_TILE * A_STRIDE * 2)     // 18432
#define W_BYTES      (CIN * W_STRIDE * 2)        // 9216
#define STAGE_BYTES  (A_BYTES + W_BYTES)         // 27648
#define SMEM_TOTAL   (2 * STAGE_BYTES)           // 55296

__device__ __half g_featH[(size_t)NFEAT_MAX * CIN];
__device__ __half g_wH[K3 * CIN * COUT];

__device__ __forceinline__ uint32_t smem_u32(const void* p) {
    return (uint32_t)__cvta_generic_to_shared(p);
}

// ---------------- pre-pass: fp32 -> fp16 ----------------
__global__ void convert_kernel(const float* __restrict__ feat,
                               const float* __restrict__ wgt,
                               int nfeat_elems, int nw_elems)
{
    const int nf4 = nfeat_elems >> 2;
    const int nw4 = nw_elems >> 2;
    for (int i = blockIdx.x * blockDim.x + threadIdx.x; i < nf4 + nw4;
         i += gridDim.x * blockDim.x) {
        if (i < nf4) {
            float4 v = ((const float4*)feat)[i];
            __half2 h0 = __floats2half2_rn(v.x, v.y);
            __half2 h1 = __floats2half2_rn(v.z, v.w);
            uint2 o; o.x = *(uint32_t*)&h0; o.y = *(uint32_t*)&h1;
            ((uint2*)g_featH)[i] = o;
        } else {
            int j = i - nf4;
            float4 v = ((const float4*)wgt)[j];
            __half2 h0 = __floats2half2_rn(v.x, v.y);
            __half2 h1 = __floats2half2_rn(v.z, v.w);
            uint2 o; o.x = *(uint32_t*)&h0; o.y = *(uint32_t*)&h1;
            ((uint2*)g_wH)[j] = o;
        }
    }
}

// ---------------- main kernel ----------------
__device__ __forceinline__ void issue_tile_copies(int k, char* smem, int bsel,
                                                  const int* __restrict__ indices,
                                                  int base, int M, int Nfeat, int t)
{
    __half* sA = (__half*)(smem + bsel * STAGE_BYTES);
    __half* sW = (__half*)(smem + bsel * STAGE_BYTES + A_BYTES);

    const int tr = t >> 3;          // 0..15
    const int tc = (t & 7) * 8;     // halves offset (16B chunk)

#pragma unroll
    for (int p = 0; p < 8; ++p) {
        int row  = tr + p * 16;
        int grow = base + row;
        int gi   = (grow < M) ? __ldg(indices + (long long)grow * K3 + k) : -1;
        if (gi < 0 || gi >= Nfeat) gi = -1;
        const __half* src = g_featH + (size_t)max(gi, 0) * CIN + tc;
        uint32_t dst = smem_u32(&sA[row * A_STRIDE + tc]);
        int sz = (gi >= 0) ? 16 : 0;
        asm volatile("cp.async.cg.shared.global [%0], [%1], 16, %2;\n"
                     :: "r"(dst), "l"(src), "r"(sz));
    }
#pragma unroll
    for (int p = 0; p < 4; ++p) {
        int row = tr + p * 16;
        const __half* src = g_wH + ((size_t)k * CIN + row) * COUT + tc;
        uint32_t dst = smem_u32(&sW[row * W_STRIDE + tc]);
        asm volatile("cp.async.cg.shared.global [%0], [%1], 16;\n"
                     :: "r"(dst), "l"(src));
    }
    asm volatile("cp.async.commit_group;\n" ::: "memory");
}

__global__ __launch_bounds__(NTHREADS, 4)
void spconv_mma_kernel(const int* __restrict__ indices,
                       float* __restrict__ out,
                       int M, int Nfeat)
{
    extern __shared__ char smem[];

    const int t    = threadIdx.x;
    const int warp = t >> 5;       // 0..3
    const int lane = t & 31;
    const int base = blockIdx.x * M_TILE;

    const int wm = warp >> 1;      // 0..1 -> m offset wm*64
    const int wn = warp & 1;       // 0..1 -> n offset wn*32

    // ---- prologue: stages 0 and 1 in flight ----
    issue_tile_copies(0, smem, 0, indices, base, M, Nfeat, t);
    issue_tile_copies(1, smem, 1, indices, base, M, Nfeat, t);

    // warp tile m64 x n32: acc[mt 0..3][n8-tile 0..3][4]
    float acc[4][4][4];
#pragma unroll
    for (int a = 0; a < 4; ++a)
#pragma unroll
        for (int b = 0; b < 4; ++b)
#pragma unroll
            for (int c = 0; c < 4; ++c) acc[a][b][c] = 0.f;

    for (int k = 0; k < K3; ++k) {
        const int bsel = k & 1;
        if (k == K3 - 1)
            asm volatile("cp.async.wait_group 0;\n" ::: "memory");
        else
            asm volatile("cp.async.wait_group 1;\n" ::: "memory");
        __syncthreads();   // stage k visible to all warps

        const uint32_t aB = smem_u32(smem + bsel * STAGE_BYTES);
        const uint32_t wB = aB + A_BYTES;

        // ---- warp tile m64 x n32 x k64 ----
#pragma unroll
        for (int ks = 0; ks < 4; ++ks) {
            uint32_t af[4][4];
#pragma unroll
            for (int mt = 0; mt < 4; ++mt) {
                int r = wm * 64 + mt * 16 + (lane & 15);
                int c = ks * 16 + ((lane >> 4) << 3);
                uint32_t addr = aB + (uint32_t)(r * A_STRIDE + c) * 2u;
                asm volatile("ldmatrix.sync.aligned.m8n8.x4.shared.b16 {%0,%1,%2,%3}, [%4];\n"
                             : "=r"(af[mt][0]), "=r"(af[mt][1]),
                               "=r"(af[mt][2]), "=r"(af[mt][3]) : "r"(addr));
            }
#pragma unroll
            for (int nt = 0; nt < 2; ++nt) {
                uint32_t b0, b1, b2, b3;
                {
                    int g    = lane >> 3;
                    int l8   = lane & 7;
                    int krow = ks * 16 + l8 + ((g & 1) << 3);
                    int ncol = wn * 32 + nt * 16 + ((g >> 1) << 3);
                    uint32_t addr = wB + (uint32_t)(krow * W_STRIDE + ncol) * 2u;
                    asm volatile("ldmatrix.sync.aligned.m8n8.x4.trans.shared.b16 {%0,%1,%2,%3}, [%4];\n"
                                 : "=r"(b0), "=r"(b1), "=r"(b2), "=r"(b3) : "r"(addr));
                }
#pragma unroll
                for (int mt = 0; mt < 4; ++mt) {
                    asm volatile("mma.sync.aligned.m16n8k16.row.col.f32.f16.f16.f32 "
                                 "{%0,%1,%2,%3},{%4,%5,%6,%7},{%8,%9},{%0,%1,%2,%3};\n"
                                 : "+f"(acc[mt][2*nt][0]), "+f"(acc[mt][2*nt][1]),
                                   "+f"(acc[mt][2*nt][2]), "+f"(acc[mt][2*nt][3])
                                 : "r"(af[mt][0]), "r"(af[mt][1]), "r"(af[mt][2]), "r"(af[mt][3]),
                                   "r"(b0), "r"(b1));
                    asm volatile("mma.sync.aligned.m16n8k16.row.col.f32.f16.f16.f32 "
                                 "{%0,%1,%2,%3},{%4,%5,%6,%7},{%8,%9},{%0,%1,%2,%3};\n"
                                 : "+f"(acc[mt][2*nt+1][0]), "+f"(acc[mt][2*nt+1][1]),
                                   "+f"(acc[mt][2*nt+1][2]), "+f"(acc[mt][2*nt+1][3])
                                 : "r"(af[mt][0]), "r"(af[mt][1]), "r"(af[mt][2]), "r"(af[mt][3]),
                                   "r"(b2), "r"(b3));
                }
            }
        }

        __syncthreads();   // all warps done with stage k's buffer
        if (k + 2 < K3)
            issue_tile_copies(k + 2, smem, bsel, indices, base, M, Nfeat, t);
    }

    // ---- epilogue: fp32 acc -> fp16 rounding (match reference) -> fp32 store ----
    {
        const int g  = lane >> 2;
        const int cc = (lane & 3) * 2;
#pragma unroll
        for (int mt = 0; mt < 4; ++mt) {
            const int row0 = base + wm * 64 + mt * 16 + g;
            const int row1 = row0 + 8;
#pragma unroll
            for (int nt8 = 0; nt8 < 4; ++nt8) {
                int col = wn * 32 + nt8 * 8 + cc;
                if (row0 < M) {
                    float2 v;
                    v.x = __half2float(__float2half_rn(acc[mt][nt8][0]));
                    v.y = __half2float(__float2half_rn(acc[mt][nt8][1]));
                    *(float2*)(out + (long long)row0 * COUT + col) = v;
                }
                if (row1 < M) {
                    float2 v;
                    v.x = __half2float(__float2half_rn(acc[mt][nt8][2]));
                    v.y = __half2float(__float2half_rn(acc[mt][nt8][3]));
                    *(float2*)(out + (long long)row1 * COUT + col) = v;
                }
            }
        }
    }
}

extern "C" void kernel_launch(void* const* d_in, const int* in_sizes, int n_in,
                              void* d_out, int out_size)
{
    const float* features = (const float*)d_in[0];
    const int*   indices  = (const int*)d_in[1];
    const float* weight   = (const float*)d_in[2];
    float*       out      = (float*)d_out;

    const int M     = out_size / COUT;       // 200000
    const int Nfeat = in_sizes[0] / CIN;     // 200000
    const int grid  = (M + M_TILE - 1) / M_TILE;

    // unconditional (no static guards): idempotent, capture-safe attribute set
    cudaFuncSetAttribute(spconv_mma_kernel,
                         cudaFuncAttributeMaxDynamicSharedMemorySize, SMEM_TOTAL);

    convert_kernel<<<1024, 256>>>(features, weight, Nfeat * CIN, K3 * CIN * COUT);
    spconv_mma_kernel<<<grid, NTHREADS, SMEM_TOTAL>>>(indices, out, M, Nfeat);
}